// round 10
// baseline (speedup 1.0000x reference)
#include <cuda_runtime.h>
#include <cstdint>

#define BB  2
#define CC  256
#define C8  32
#define HH  64
#define WW  64
#define NN  4096
#define KIM 2304
#define EPSI 1e-5f

#define TQ  128     // queries per flash CTA
#define TK  64      // keys per flash tile
#define CHF 128     // channels per flash CTA (c-half)

// ---------------------------------------------------------------------------
// Scratch
// ---------------------------------------------------------------------------
__device__ __align__(128) float g_col [(long)BB * KIM * NN];  // im2col buffer
__device__ __align__(128) float g_QK [BB * 64 * NN];          // packed Q(0-31)/K(32-63)
__device__ __align__(128) float g_V  [BB * CC * NN];
__device__ __align__(128) float g_Wp [64 * CC];
__device__ __align__(128) float g_Bp [64];
__device__ __align__(128) float g_t1[BB * CC * NN];
__device__ __align__(128) float g_t2[BB * CC * NN];
__device__ __align__(128) float g_t3[BB * CC * NN];
__device__ __align__(128) float g_t4[BB * CC * NN];
__device__ __align__(128) float g_t5[BB * CC * NN];

// ---------------------------------------------------------------------------
// cp.async / mma helpers
// ---------------------------------------------------------------------------
__device__ __forceinline__ void cp_async16(float* smem, const float* gmem, bool pred)
{
    uint32_t s = (uint32_t)__cvta_generic_to_shared(smem);
    int sz = pred ? 16 : 0;
    asm volatile("cp.async.cg.shared.global [%0], [%1], 16, %2;\n"
                 :: "r"(s), "l"(gmem), "r"(sz));
}
__device__ __forceinline__ void cp_commit() { asm volatile("cp.async.commit_group;\n"); }
template<int W> __device__ __forceinline__ void cp_wait()
{ asm volatile("cp.async.wait_group %0;\n" :: "n"(W)); }

__device__ __forceinline__ void mma_tf32(float c[4], const uint32_t a[4], const uint32_t b[2])
{
    asm volatile(
        "mma.sync.aligned.m16n8k8.row.col.f32.tf32.tf32.f32 "
        "{%0,%1,%2,%3}, {%4,%5,%6,%7}, {%8,%9}, {%0,%1,%2,%3};\n"
        : "+f"(c[0]), "+f"(c[1]), "+f"(c[2]), "+f"(c[3])
        : "r"(a[0]), "r"(a[1]), "r"(a[2]), "r"(a[3]), "r"(b[0]), "r"(b[1]));
}

// ---------------------------------------------------------------------------
// TF32 tensor-core GEMM (projections + conv)
// ---------------------------------------------------------------------------
#define BK 32
#define BN 128

template<bool TA, bool TB, int BM>
__global__ __launch_bounds__(256, 2)
void gemm_tc(const float* __restrict__ A, const float* __restrict__ B,
             float* __restrict__ C, const float* __restrict__ bias,
             int M, int N, int K, int lda, int ldb, int ldc,
             long sA, long sB, long sC)
{
    constexpr int ASZ = TA ? BK * (BM + 4) : BM * 36;
    constexpr int BSZ = TB ? BN * 36      : BK * (BN + 4);
    constexpr int MT  = BM / 32;

    extern __shared__ float dynsm[];
    float* sAb = dynsm;
    float* sBb = dynsm + 2 * ASZ;

    A += blockIdx.z * sA;
    B += blockIdx.z * sB;
    C += blockIdx.z * sC;

    const int row0 = blockIdx.y * BM;
    const int col0 = blockIdx.x * BN;
    const int tid  = threadIdx.x;
    const int lane = tid & 31, w = tid >> 5;
    const int warpM = w >> 2, warpN = w & 3;
    const int gid = lane >> 2, tig = lane & 3;

    auto loadA = [&](int buf, int k0) {
        float* sa = sAb + buf * ASZ;
        #pragma unroll
        for (int i = 0; i < BM / 32; i++) {
            int q = tid + i * 256;
            if (!TA) {
                int m = q >> 3, kq = q & 7;
                cp_async16(sa + m * 36 + kq * 4,
                           A + (long)(row0 + m) * lda + k0 + kq * 4,
                           row0 + m < M);
            } else {
                int k = q / (BM / 4), mq = q % (BM / 4);
                cp_async16(sa + k * (BM + 4) + mq * 4,
                           A + (long)(k0 + k) * lda + row0 + mq * 4,
                           row0 + mq * 4 < M);
            }
        }
    };
    auto loadB = [&](int buf, int k0) {
        float* sb = sBb + buf * BSZ;
        #pragma unroll
        for (int i = 0; i < 4; i++) {
            int q = tid + i * 256;
            if (!TB) {
                int k = q >> 5, nq = q & 31;
                cp_async16(sb + k * (BN + 4) + nq * 4,
                           B + (long)(k0 + k) * ldb + col0 + nq * 4, true);
            } else {
                int n = q >> 3, kq = q & 7;
                cp_async16(sb + n * 36 + kq * 4,
                           B + (long)(col0 + n) * ldb + k0 + kq * 4, true);
            }
        }
    };

    float acc[MT][4][4] = {};
    const int nIter = K / BK;

    loadA(0, 0); loadB(0, 0);
    cp_commit();

    for (int it = 0; it < nIter; it++) {
        if (it + 1 < nIter) { loadA((it + 1) & 1, (it + 1) * BK);
                              loadB((it + 1) & 1, (it + 1) * BK); }
        cp_commit();
        cp_wait<1>();
        __syncthreads();

        const uint32_t* pa = (const uint32_t*)(sAb + (it & 1) * ASZ);
        const uint32_t* pb = (const uint32_t*)(sBb + (it & 1) * BSZ);

        #pragma unroll
        for (int k8 = 0; k8 < 4; k8++) {
            uint32_t a[MT][4], b[4][2];
            #pragma unroll
            for (int mt = 0; mt < MT; mt++) {
                int m = warpM * (BM / 2) + mt * 16;
                if (!TA) {
                    a[mt][0] = pa[(m + gid)     * 36 + k8 * 8 + tig];
                    a[mt][1] = pa[(m + gid + 8) * 36 + k8 * 8 + tig];
                    a[mt][2] = pa[(m + gid)     * 36 + k8 * 8 + tig + 4];
                    a[mt][3] = pa[(m + gid + 8) * 36 + k8 * 8 + tig + 4];
                } else {
                    a[mt][0] = pa[(k8 * 8 + tig)     * (BM + 4) + m + gid];
                    a[mt][1] = pa[(k8 * 8 + tig)     * (BM + 4) + m + gid + 8];
                    a[mt][2] = pa[(k8 * 8 + tig + 4) * (BM + 4) + m + gid];
                    a[mt][3] = pa[(k8 * 8 + tig + 4) * (BM + 4) + m + gid + 8];
                }
            }
            #pragma unroll
            for (int nt = 0; nt < 4; nt++) {
                int n = warpN * 32 + nt * 8;
                if (!TB) {
                    b[nt][0] = pb[(k8 * 8 + tig)     * (BN + 4) + n + gid];
                    b[nt][1] = pb[(k8 * 8 + tig + 4) * (BN + 4) + n + gid];
                } else {
                    b[nt][0] = pb[(n + gid) * 36 + k8 * 8 + tig];
                    b[nt][1] = pb[(n + gid) * 36 + k8 * 8 + tig + 4];
                }
            }
            #pragma unroll
            for (int mt = 0; mt < MT; mt++)
                #pragma unroll
                for (int nt = 0; nt < 4; nt++)
                    mma_tf32(acc[mt][nt], a[mt], b[nt]);
        }
        __syncthreads();
    }

    #pragma unroll
    for (int mt = 0; mt < MT; mt++) {
        int r0 = row0 + warpM * (BM / 2) + mt * 16 + gid;
        #pragma unroll
        for (int half = 0; half < 2; half++) {
            int r = r0 + half * 8;
            if (r >= M) continue;
            float bv = bias ? bias[r] : 0.f;
            #pragma unroll
            for (int nt = 0; nt < 4; nt++) {
                int c = col0 + warpN * 32 + nt * 8 + tig * 2;
                float v0 = acc[mt][nt][half * 2 + 0] + bv;
                float v1 = acc[mt][nt][half * 2 + 1] + bv;
                *(float2*)&C[(long)r * ldc + c] = make_float2(v0, v1);
            }
        }
    }
}

// ---------------------------------------------------------------------------
// Flash attention, 512 threads (16 warps -> 4/SMSP for latency hiding).
// out[c,q] = gamma * (sum_m V[c,m] exp(S[q,m])) / rowsum + resid
// QK partition: 4 warps in q (32 each) x 4 in k (16 each)
// AV partition: 4 warps in c (32 each) x 4 in q (32 each)
// ---------------------------------------------------------------------------
__global__ __launch_bounds__(512, 1)
void flash_k(const float* __restrict__ QK, const float* __restrict__ V,
             const float* __restrict__ gamma, const float* __restrict__ resid,
             float* __restrict__ out)
{
    extern __shared__ float sm[];
    float* Qs   = sm;            // 128*36            = 4608
    float* Ks   = sm + 4608;     // 2 * 32*68         = 4352
    float* Vs   = sm + 8960;     // 2 * 128*68        = 17408
    float* Ps   = sm + 26368;    // 128*68            = 8704
    float* rsum = sm + 35072;    // 128
    float* rinv = sm + 35200;    // 128

    const int b  = blockIdx.z;
    const int q0 = blockIdx.x * TQ;
    const float* Qg = QK + (long)b * 64 * NN;
    const float* Kg = Qg + 32 * NN;
    const float* Vg = V     + (long)b * CC * NN + (long)blockIdx.y * CHF * NN;
    const float* rg = resid + (long)b * CC * NN + (long)blockIdx.y * CHF * NN;
    float*       og = out   + (long)b * CC * NN + (long)blockIdx.y * CHF * NN;

    const int tid  = threadIdx.x;
    const int lane = tid & 31, w = tid >> 5;
    const int gid  = lane >> 2, tig = lane & 3;
    const int wq_qk = (w >> 2) * 32;   // QK: 4 warps in q
    const int wk_qk = (w & 3) * 16;    //     4 warps in k
    const int wc_av = (w & 3) * 32;    // AV: 4 warps in c
    const int wq_av = (w >> 2) * 32;   //     4 warps in q

    // Q tile transposed: Qs[q][d]
    #pragma unroll
    for (int i = 0; i < 8; i++) {
        int idx = tid + i * 512;
        int d = idx >> 7, q = idx & 127;
        Qs[q * 36 + d] = Qg[(long)d * NN + q0 + q];
    }
    if (tid < 128) rsum[tid] = 0.f;
    __syncthreads();

    // hoist Q a-fragments (fixed for whole CTA)
    uint32_t qa[2][4][4];
    const uint32_t* Qsu = (const uint32_t*)Qs;
    #pragma unroll
    for (int mt = 0; mt < 2; mt++)
        #pragma unroll
        for (int k8 = 0; k8 < 4; k8++) {
            int m = wq_qk + mt * 16;
            qa[mt][k8][0] = Qsu[(m + gid)     * 36 + k8 * 8 + tig];
            qa[mt][k8][1] = Qsu[(m + gid + 8) * 36 + k8 * 8 + tig];
            qa[mt][k8][2] = Qsu[(m + gid)     * 36 + k8 * 8 + tig + 4];
            qa[mt][k8][3] = Qsu[(m + gid + 8) * 36 + k8 * 8 + tig + 4];
        }

    float acc[2][4][4] = {};

    auto loadKV = [&](int buf, int m0) {
        {   // K: 32 rows x 16 cp16 = 512 ops, one per thread
            int d = tid >> 4, j4 = (tid & 15) * 4;
            cp_async16(Ks + buf * 2176 + d * 68 + j4, Kg + (long)d * NN + m0 + j4, true);
        }
        #pragma unroll
        for (int i = 0; i < 4; i++) {  // V: 128 rows x 16 cp16
            int idx = tid + i * 512;
            int c = idx >> 4, j4 = (idx & 15) * 4;
            cp_async16(Vs + buf * 8704 + c * 68 + j4, Vg + (long)c * NN + m0 + j4, true);
        }
        cp_commit();
    };

    loadKV(0, 0);

    for (int t = 0; t < NN / TK; t++) {
        const int buf = t & 1;
        if (t + 1 < NN / TK) loadKV(buf ^ 1, (t + 1) * TK);
        cp_wait<1>();
        __syncthreads();

        // ---- QK: S[128q x 64k], warp covers 32q x 16k ----
        const uint32_t* Ku = (const uint32_t*)(Ks + buf * 2176);
        float sacc[2][2][4] = {};
        #pragma unroll
        for (int k8 = 0; k8 < 4; k8++) {
            uint32_t bfr[2][2];
            #pragma unroll
            for (int nt = 0; nt < 2; nt++) {
                int n = wk_qk + nt * 8;
                bfr[nt][0] = Ku[(k8 * 8 + tig)     * 68 + n + gid];
                bfr[nt][1] = Ku[(k8 * 8 + tig + 4) * 68 + n + gid];
            }
            #pragma unroll
            for (int mt = 0; mt < 2; mt++)
                #pragma unroll
                for (int nt = 0; nt < 2; nt++)
                    mma_tf32(sacc[mt][nt], qa[mt][k8], bfr[nt]);
        }
        // exp -> P smem
        #pragma unroll
        for (int mt = 0; mt < 2; mt++)
            #pragma unroll
            for (int nt = 0; nt < 2; nt++) {
                int r = wq_qk + mt * 16 + gid;
                int c = wk_qk + nt * 8 + tig * 2;
                *(float2*)&Ps[r * 68 + c] =
                    make_float2(__expf(sacc[mt][nt][0]), __expf(sacc[mt][nt][1]));
                *(float2*)&Ps[(r + 8) * 68 + c] =
                    make_float2(__expf(sacc[mt][nt][2]), __expf(sacc[mt][nt][3]));
            }
        __syncthreads();

        // row sums of this P tile (4 threads per row)
        {
            int r = tid >> 2, q16 = (tid & 3) * 16;
            float s = 0.f;
            #pragma unroll 4
            for (int j = 0; j < 16; j++) s += Ps[r * 68 + q16 + j];
            atomicAdd(&rsum[r], s);
        }

        // ---- AV: acc[c,q] += V[c,m] * P[q,m], warp covers 32c x 32q ----
        const uint32_t* Vu = (const uint32_t*)(Vs + buf * 8704);
        const uint32_t* Pu = (const uint32_t*)Ps;
        #pragma unroll
        for (int k8 = 0; k8 < 8; k8++) {
            uint32_t av[2][4], bv[4][2];
            #pragma unroll
            for (int mt = 0; mt < 2; mt++) {
                int m = wc_av + mt * 16;
                av[mt][0] = Vu[(m + gid)     * 68 + k8 * 8 + tig];
                av[mt][1] = Vu[(m + gid + 8) * 68 + k8 * 8 + tig];
                av[mt][2] = Vu[(m + gid)     * 68 + k8 * 8 + tig + 4];
                av[mt][3] = Vu[(m + gid + 8) * 68 + k8 * 8 + tig + 4];
            }
            #pragma unroll
            for (int nt = 0; nt < 4; nt++) {
                int n = wq_av + nt * 8;
                bv[nt][0] = Pu[(n + gid) * 68 + k8 * 8 + tig];
                bv[nt][1] = Pu[(n + gid) * 68 + k8 * 8 + tig + 4];
            }
            #pragma unroll
            for (int mt = 0; mt < 2; mt++)
                #pragma unroll
                for (int nt = 0; nt < 4; nt++)
                    mma_tf32(acc[mt][nt], av[mt], bv[nt]);
        }
        __syncthreads();   // protect buf & Ps before next iteration's writes
    }

    if (tid < 128) rinv[tid] = 1.f / rsum[tid];
    __syncthreads();

    const float gm = gamma[0];
    #pragma unroll
    for (int mt = 0; mt < 2; mt++) {
        int c0 = wc_av + mt * 16 + gid;
        #pragma unroll
        for (int nt = 0; nt < 4; nt++) {
            int ql = wq_av + nt * 8 + tig * 2;
            float i0 = rinv[ql], i1 = rinv[ql + 1];
            int qg = q0 + ql;
            float v0 = gm * acc[mt][nt][0] * i0 + rg[(long)c0 * NN + qg];
            float v1 = gm * acc[mt][nt][1] * i1 + rg[(long)c0 * NN + qg + 1];
            *(float2*)&og[(long)c0 * NN + qg] = make_float2(v0, v1);
            int c1 = c0 + 8;
            float v2 = gm * acc[mt][nt][2] * i0 + rg[(long)c1 * NN + qg];
            float v3 = gm * acc[mt][nt][3] * i1 + rg[(long)c1 * NN + qg + 1];
            *(float2*)&og[(long)c1 * NN + qg] = make_float2(v2, v3);
        }
    }
}

// ---------------------------------------------------------------------------
// pack wq/wk into one [64,256] weight + [64] bias
// ---------------------------------------------------------------------------
__global__ void pack_qk(const float* __restrict__ wq, const float* __restrict__ bq,
                        const float* __restrict__ wk, const float* __restrict__ bk,
                        float* __restrict__ wp, float* __restrict__ bp)
{
    int i = blockIdx.x * 256 + threadIdx.x;
    if (i < 64 * 256) {
        int r = i >> 8;
        wp[i] = (r < 32) ? wq[i] : wk[i - 32 * 256];
    }
    if (i < 64) bp[i] = (i < 32) ? bq[i] : bk[i - 32];
}

// ---------------------------------------------------------------------------
// im2col
// ---------------------------------------------------------------------------
__global__ void im2col_k(const float* __restrict__ x, float* __restrict__ col)
{
    long idx = blockIdx.x * 256L + threadIdx.x;
    if (idx >= (long)KIM * NN) return;
    int n = (int)(idx & (NN - 1));
    int k = (int)(idx >> 12);
    int c = k / 9, r = k % 9;
    int h = (n >> 6) + r / 3 - 1;
    int w2 = (n & 63) + r % 3 - 1;
    const float* xb = x + blockIdx.z * (long)CC * NN;
    float v = 0.f;
    if (h >= 0 && h < HH && w2 >= 0 && w2 < WW)
        v = xb[(long)c * NN + h * WW + w2];
    col[blockIdx.z * (long)KIM * NN + idx] = v;
}

// ---------------------------------------------------------------------------
// InstanceNorm per (b,c) plane, optional fused residual add. float4 I/O.
// ---------------------------------------------------------------------------
__global__ void inorm_k(const float* __restrict__ a, const float* __restrict__ b,
                        float* __restrict__ out)
{
    __shared__ float4 vals[NN / 4];
    __shared__ float red[256];
    const long base4 = (long)blockIdx.x * (NN / 4);
    const int tid = threadIdx.x;
    const float4* a4 = (const float4*)a;
    const float4* b4 = (const float4*)b;
    float4* o4 = (float4*)out;

    float s = 0.f, s2 = 0.f;
    for (int i = tid; i < NN / 4; i += 256) {
        float4 v = a4[base4 + i];
        if (b) {
            float4 u = b4[base4 + i];
            v.x += u.x; v.y += u.y; v.z += u.z; v.w += u.w;
        }
        vals[i] = v;
        s  += v.x + v.y + v.z + v.w;
        s2 += v.x * v.x + v.y * v.y + v.z * v.z + v.w * v.w;
    }
    red[tid] = s; __syncthreads();
    for (int st = 128; st > 0; st >>= 1) {
        if (tid < st) red[tid] += red[tid + st];
        __syncthreads();
    }
    float mean = red[0] * (1.0f / NN);
    __syncthreads();
    red[tid] = s2; __syncthreads();
    for (int st = 128; st > 0; st >>= 1) {
        if (tid < st) red[tid] += red[tid + st];
        __syncthreads();
    }
    float var = red[0] * (1.0f / NN) - mean * mean;
    float scale = rsqrtf(var + EPSI);

    for (int i = tid; i < NN / 4; i += 256) {
        float4 v = vals[i];
        v.x = (v.x - mean) * scale; v.y = (v.y - mean) * scale;
        v.z = (v.z - mean) * scale; v.w = (v.w - mean) * scale;
        o4[base4 + i] = v;
    }
}

// ---------------------------------------------------------------------------
// Host driver
// ---------------------------------------------------------------------------
static float* symaddr(const void* sym)
{
    void* p = nullptr;
    cudaGetSymbolAddress(&p, sym);
    return (float*)p;
}

extern "C" void kernel_launch(void* const* d_in, const int* in_sizes, int n_in,
                              void* d_out, int out_size)
{
    int idx = 0;
    const float* x = (const float*)d_in[idx++];
    const float* y = (const float*)d_in[idx++];

    struct AttnP { const float *wq, *bq, *wk, *bk, *wv, *bv, *gamma; };
    AttnP P[3];
    for (int p = 0; p < 3; p++) {
        P[p].wq    = (const float*)d_in[idx++];
        P[p].bq    = (const float*)d_in[idx++];
        P[p].wk    = (const float*)d_in[idx++];
        P[p].bk    = (const float*)d_in[idx++];
        P[p].wv    = (const float*)d_in[idx++];
        P[p].bv    = (const float*)d_in[idx++];
        P[p].gamma = (const float*)d_in[idx++];
    }
    const float* conv1_w = (const float*)d_in[idx++];
    const float* conv1_b = (const float*)d_in[idx++];
    const float* conv2_w = (const float*)d_in[idx++];
    const float* conv2_b = (const float*)d_in[idx++];

    float* col = symaddr(g_col);
    float* QKb = symaddr(g_QK);
    float* V   = symaddr(g_V);
    float* Wp  = symaddr(g_Wp);
    float* Bp  = symaddr(g_Bp);
    float* t1  = symaddr(g_t1);
    float* t2  = symaddr(g_t2);
    float* t3  = symaddr(g_t3);
    float* t4  = symaddr(g_t4);
    float* t5  = symaddr(g_t5);

    const int smProj  = 2 * (64 * 36 + 32 * 132) * 4;    // gemm_tc<0,0,64>
    const int smBig   = 2 * (128 * 36 + 32 * 132) * 4;   // gemm_tc<0,0,128> = 70656
    const int smFlash = 35328 * 4;                       // 141312 B
    cudaFuncSetAttribute(gemm_tc<false, false, 64>,
        cudaFuncAttributeMaxDynamicSharedMemorySize, smProj);
    cudaFuncSetAttribute(gemm_tc<false, false, 128>,
        cudaFuncAttributeMaxDynamicSharedMemorySize, smBig);
    cudaFuncSetAttribute(flash_k,
        cudaFuncAttributeMaxDynamicSharedMemorySize, smFlash);

    auto attn = [&](const float* xin, const float* vin, const float* resid,
                    const AttnP& p, float* outbuf)
    {
        pack_qk<<<64, 256>>>(p.wq, p.bq, p.wk, p.bk, Wp, Bp);
        // [Q;K] = Wp @ xin + Bp   [64 x 4096] per batch
        gemm_tc<false, false, 64><<<dim3(32, 1, BB), 256, smProj>>>(
            Wp, xin, QKb, Bp,
            64, NN, CC, CC, NN, NN, 0L, (long)CC * NN, (long)64 * NN);
        // V = wv @ vin + bv   (BM=128: 2 fat row-tiles)
        gemm_tc<false, false, 128><<<dim3(32, 2, BB), 256, smBig>>>(
            p.wv, vin, V, p.bv,
            CC, NN, CC, CC, NN, NN, 0L, (long)CC * NN, (long)CC * NN);
        // fused attention (QK^T -> exp -> rowsum -> AV -> gamma*.+resid)
        flash_k<<<dim3(NN / TQ, 2, BB), 512, smFlash>>>(
            QKb, V, p.gamma, resid, outbuf);
    };

    auto conv = [&](const float* in, const float* w, const float* b, float* out)
    {
        im2col_k<<<dim3(((long)KIM * NN + 255) / 256, 1, BB), 256>>>(in, col);
        gemm_tc<false, false, 128><<<dim3(32, 2, BB), 256, smBig>>>(
            w, col, out, b,
            CC, NN, KIM, KIM, NN, NN, 0L, (long)KIM * NN, (long)CC * NN);
    };

    // Phase A: out_1 = inorm(self_attn(x, sa1))
    attn(x, x, x, P[0], t1);
    inorm_k<<<BB * CC, 256>>>(t1, nullptr, t2);            // t2 = out_1

    // Phase B: out_2 = inorm(out_1 + conv1(out_1))
    conv(t2, conv1_w, conv1_b, t3);
    inorm_k<<<BB * CC, 256>>>(t2, t3, t4);                 // t4 = out_2

    // Phase C: out_3 = inorm(self_attn(y, sa2))
    attn(y, y, y, P[1], t1);
    inorm_k<<<BB * CC, 256>>>(t1, nullptr, t5);            // t5 = out_3

    // Phase D: top attention (qk from out_2, v from out_3, resid y)
    attn(t4, t5, y, P[2], t1);
    inorm_k<<<BB * CC, 256>>>(t1, nullptr, t2);
    inorm_k<<<BB * CC, 256>>>(t2, t5, t3);
    conv(t3, conv2_w, conv2_b, t1);
    inorm_k<<<BB * CC, 256>>>(t3, t1, (float*)d_out);
}